// round 14
// baseline (speedup 1.0000x reference)
#include <cuda_runtime.h>
#include <cuda_bf16.h>
#include <stdint.h>

#define NS 50000
#define ES 1000000
#define EA 500000

// Scratch (allocation-free rule): device globals, 16B-aligned.
__device__ __align__(16) float g_sum_u[NS * 64];
__device__ __align__(16) float g_sum_x[NS * 64];
__device__ float g_deg[NS];

// ---------------------------------------------------------------------------
__device__ __forceinline__ float rcp_fma(float d) {
    float r = __int_as_float(0x7EF311C3 - __float_as_int(d));
    r = r * fmaf(-d, r, 2.0f);
    r = r * fmaf(-d, r, 2.0f);
    r = r * fmaf(-d, r, 2.0f);
    return r;
}
__device__ __forceinline__ float my_tanh(float v) {
    float x = fminf(fmaxf(v, -7.90531110f), 7.90531110f);
    float x2 = x * x;
    float p = -2.76076847742355e-16f;
    p = fmaf(p, x2, 2.00018790482477e-13f);
    p = fmaf(p, x2, -8.60467152213735e-11f);
    p = fmaf(p, x2, 5.12229709037114e-08f);
    p = fmaf(p, x2, 1.48572235717979e-05f);
    p = fmaf(p, x2, 6.37261928875436e-04f);
    p = fmaf(p, x2, 4.89352455891786e-03f);
    float q = 1.19825839466702e-06f;
    q = fmaf(q, x2, 1.18534705686654e-04f);
    q = fmaf(q, x2, 2.26843463243900e-03f);
    q = fmaf(q, x2, 4.89352518554385e-03f);
    return (x * p) * rcp_fma(q);
}
// split pair (a=even idx, b=odd idx) into bf16x2 hi/lo planes (low half = even)
__device__ __forceinline__ void split2(float a, float b, uint32_t& hi, uint32_t& lo) {
    __nv_bfloat16 ah = __float2bfloat16(a), bh = __float2bfloat16(b);
    float ar = a - __bfloat162float(ah), br = b - __bfloat162float(bh);
    __nv_bfloat16 al = __float2bfloat16(ar), bl = __float2bfloat16(br);
    hi = ((uint32_t)__bfloat16_as_ushort(bh) << 16) | (uint32_t)__bfloat16_as_ushort(ah);
    lo = ((uint32_t)__bfloat16_as_ushort(bl) << 16) | (uint32_t)__bfloat16_as_ushort(al);
}
__device__ __forceinline__ void mma_bf16(float c[4], uint32_t a0, uint32_t a1,
                                         uint32_t a2, uint32_t a3,
                                         uint32_t b0, uint32_t b1) {
    asm volatile("mma.sync.aligned.m16n8k16.row.col.f32.bf16.bf16.f32 "
        "{%0,%1,%2,%3}, {%4,%5,%6,%7}, {%8,%9}, {%0,%1,%2,%3};"
        : "+f"(c[0]), "+f"(c[1]), "+f"(c[2]), "+f"(c[3])
        : "r"(a0), "r"(a1), "r"(a2), "r"(a3), "r"(b0), "r"(b1));
}
__device__ __forceinline__ void red2(float* p, float a, float b) {
    asm volatile("red.global.add.v2.f32 [%0], {%1,%2};" :: "l"(p), "f"(a), "f"(b) : "memory");
}

// Stage W[k][64] -> Wt[n][kpad] (bf16 hi/lo words), row stride WSw words.
__device__ void stage_W(const float* __restrict__ W, uint32_t* wh, uint32_t* wl,
                        int Kin, int WSw, int tid, int nt) {
    for (int idx = tid; idx < 64 * WSw; idx += nt) {
        int n = idx / WSw, kw = idx % WSw;
        int k0 = kw * 2;
        float v0 = (k0 < Kin) ? W[(size_t)k0 * 64 + n] : 0.0f;
        float v1 = (k0 + 1 < Kin) ? W[(size_t)(k0 + 1) * 64 + n] : 0.0f;
        uint32_t hi, lo;
        split2(v0, v1, hi, lo);
        wh[idx] = hi; wl[idx] = lo;
    }
}

// Layer with A in smem (3-term bf16-split accumulate).
__device__ __forceinline__ void layer_smem(float acc[8][4],
    const uint32_t* Ah, const uint32_t* Al, int ASw, int rowbase,
    const uint32_t* Wh, const uint32_t* Wl, int WSw, int kchunks, int lane)
{
    int g = lane >> 2, c = lane & 3;
#pragma unroll
    for (int i = 0; i < 8; i++)
#pragma unroll
        for (int j = 0; j < 4; j++) acc[i][j] = 0.0f;
    const uint32_t* a0p = Ah + (rowbase + g) * ASw + c;
    const uint32_t* a1p = Ah + (rowbase + g + 8) * ASw + c;
    const uint32_t* l0p = Al + (rowbase + g) * ASw + c;
    const uint32_t* l1p = Al + (rowbase + g + 8) * ASw + c;
    for (int kc = 0; kc < kchunks; kc++) {
        uint32_t ah0 = a0p[kc * 8], ah1 = a1p[kc * 8];
        uint32_t ah2 = a0p[kc * 8 + 4], ah3 = a1p[kc * 8 + 4];
        uint32_t al0 = l0p[kc * 8], al1 = l1p[kc * 8];
        uint32_t al2 = l0p[kc * 8 + 4], al3 = l1p[kc * 8 + 4];
#pragma unroll
        for (int nt2 = 0; nt2 < 8; nt2++) {
            const uint32_t* bh = Wh + (nt2 * 8 + g) * WSw + kc * 8 + c;
            const uint32_t* bl = Wl + (nt2 * 8 + g) * WSw + kc * 8 + c;
            uint32_t bh0 = bh[0], bh1 = bh[4];
            uint32_t bl0 = bl[0], bl1 = bl[4];
            mma_bf16(acc[nt2], ah0, ah1, ah2, ah3, bh0, bh1);
            mma_bf16(acc[nt2], ah0, ah1, ah2, ah3, bl0, bl1);
            mma_bf16(acc[nt2], al0, al1, al2, al3, bh0, bh1);
        }
    }
}

// Layer with activations in registers (C-frag == A-frag layout), K=64 (4 chunks).
__device__ __forceinline__ void layer_regs(float acc[8][4],
    const uint32_t zh[16], const uint32_t zl[16],
    const uint32_t* Wh, const uint32_t* Wl, int lane)   // WSw = 36
{
    int g = lane >> 2, c = lane & 3;
#pragma unroll
    for (int i = 0; i < 8; i++)
#pragma unroll
        for (int j = 0; j < 4; j++) acc[i][j] = 0.0f;
#pragma unroll
    for (int kc = 0; kc < 4; kc++) {
        uint32_t ah0 = zh[4 * kc + 0], ah1 = zh[4 * kc + 1];
        uint32_t ah2 = zh[4 * kc + 2], ah3 = zh[4 * kc + 3];
        uint32_t al0 = zl[4 * kc + 0], al1 = zl[4 * kc + 1];
        uint32_t al2 = zl[4 * kc + 2], al3 = zl[4 * kc + 3];
#pragma unroll
        for (int nt2 = 0; nt2 < 8; nt2++) {
            const uint32_t* bh = Wh + (nt2 * 8 + g) * 36 + kc * 8 + c;
            const uint32_t* bl = Wl + (nt2 * 8 + g) * 36 + kc * 8 + c;
            uint32_t bh0 = bh[0], bh1 = bh[4];
            uint32_t bl0 = bl[0], bl1 = bl[4];
            mma_bf16(acc[nt2], ah0, ah1, ah2, ah3, bh0, bh1);
            mma_bf16(acc[nt2], ah0, ah1, ah2, ah3, bl0, bl1);
            mma_bf16(acc[nt2], al0, al1, al2, al3, bh0, bh1);
        }
    }
}

// bias + tanh + bf16-split pack: acc -> next-layer A-frags (registers).
__device__ __forceinline__ void epi(const float acc[8][4], const float* bias,
                                    uint32_t zh[16], uint32_t zl[16], int lane)
{
    int c2 = (lane & 3) * 2;
#pragma unroll
    for (int nt2 = 0; nt2 < 8; nt2++) {
        float2 b = *(const float2*)(bias + nt2 * 8 + c2);
        float t0 = my_tanh(acc[nt2][0] + b.x);
        float t1 = my_tanh(acc[nt2][1] + b.y);
        float t2 = my_tanh(acc[nt2][2] + b.x);
        float t3 = my_tanh(acc[nt2][3] + b.y);
        split2(t0, t1, zh[2 * nt2 + 0], zl[2 * nt2 + 0]);
        split2(t2, t3, zh[2 * nt2 + 1], zl[2 * nt2 + 1]);
    }
}

// ---------------------------------------------------------------------------
__global__ void zero_kernel(void) {
    int i = blockIdx.x * blockDim.x + threadIdx.x;
    if (i < NS * 64) { g_sum_u[i] = 0.0f; g_sum_x[i] = 0.0f; }
    if (i < NS) g_deg[i] = 0.0f;
}

// ---------------------------------------------------------------------------
// s2s: 77->64->64->64. A stride 44 words, W1 stride 44, kchunks=5.
// Software-pipelined: double-buffered A tiles, gather split 2 threads/row.
#define S_W1H 0
#define S_W1L 11264
#define S_W2H 22528
#define S_W2L 31744
#define S_W3H 40960
#define S_W3L 50176
#define S_AH0 59392
#define S_AL0 70656
#define S_AH1 81920
#define S_AL1 93184
#define S_B1  104448
#define S_B2  104704
#define S_B3  104960
#define S_DST0 105216
#define S_DST1 105472
#define S2S_SMEM 105728

// half0 loads: ps, pd, dis, x (2 f4), h4[0..6]  -> writes words 0..19
// half1 loads: h4[6..15]                        -> writes words 20..39
__device__ __forceinline__ void s2s_load(int half, int s, int d, int ec,
    const float* __restrict__ pos_state, const float* __restrict__ xin,
    const float* __restrict__ hbuf, const float* __restrict__ edis,
    float4 st[10], float2& sp0, float2& sp1, float& sdis)
{
    const float4* h4 = (const float4*)(hbuf + 64 * (size_t)s);
    if (half == 0) {
        sp0 = *(const float2*)(pos_state + 2 * (size_t)s);
        sp1 = *(const float2*)(pos_state + 2 * (size_t)d);
        sdis = edis[ec];
        const float4* x4 = (const float4*)(xin + 8 * (size_t)s);
        st[0] = x4[0]; st[1] = x4[1];
#pragma unroll
        for (int i = 0; i < 7; i++) st[2 + i] = h4[i];
    } else {
#pragma unroll
        for (int i = 0; i < 10; i++) st[i] = h4[6 + i];
    }
}

__device__ __forceinline__ void s2s_store(int half, int row,
    uint32_t* Ahp, uint32_t* Alp,
    const float4 st[10], float2 sp0, float2 sp1, float sdis)
{
    uint32_t* rh = Ahp + row * 44;
    uint32_t* rl = Alp + row * 44;
    uint32_t hi, lo;
    if (half == 0) {
        split2(sp0.x, sp0.y, hi, lo); rh[0] = hi; rl[0] = lo;
        split2(sp1.x, sp1.y, hi, lo); rh[1] = hi; rl[1] = lo;
        split2(sdis, st[0].x, hi, lo); rh[2] = hi; rl[2] = lo;
        split2(st[0].y, st[0].z, hi, lo); rh[3] = hi; rl[3] = lo;
        split2(st[0].w, st[1].x, hi, lo); rh[4] = hi; rl[4] = lo;
        split2(st[1].y, st[1].z, hi, lo); rh[5] = hi; rl[5] = lo;
        float prev = st[1].w;
#pragma unroll
        for (int i = 0; i < 7; i++) {
            float4 f = st[2 + i];
            split2(prev, f.x, hi, lo); rh[6 + 2 * i] = hi; rl[6 + 2 * i] = lo;
            split2(f.y, f.z, hi, lo);  rh[7 + 2 * i] = hi; rl[7 + 2 * i] = lo;
            prev = f.w;
        }
    } else {
        float prev = st[0].w;   // h[27]
#pragma unroll
        for (int i = 1; i < 10; i++) {
            float4 f = st[i];
            split2(prev, f.x, hi, lo); rh[18 + 2 * i] = hi; rl[18 + 2 * i] = lo;
            split2(f.y, f.z, hi, lo);  rh[19 + 2 * i] = hi; rl[19 + 2 * i] = lo;
            prev = f.w;
        }
        split2(prev, 0.0f, hi, lo); rh[38] = hi; rl[38] = lo;
        rh[39] = 0; rl[39] = 0;
    }
}

__global__ void __launch_bounds__(128, 2) s2s_kernel(
    const float* __restrict__ pos_state, const float* __restrict__ xin,
    const float* __restrict__ hbuf,
    const int* __restrict__ esrc, const int* __restrict__ edst,
    const float* __restrict__ edis,
    const float* __restrict__ W1, const float* __restrict__ B1,
    const float* __restrict__ W2, const float* __restrict__ B2,
    const float* __restrict__ W3, const float* __restrict__ B3)
{
    extern __shared__ char sm[];
    uint32_t* W1h = (uint32_t*)(sm + S_W1H);
    uint32_t* W1l = (uint32_t*)(sm + S_W1L);
    uint32_t* W2h = (uint32_t*)(sm + S_W2H);
    uint32_t* W2l = (uint32_t*)(sm + S_W2L);
    uint32_t* W3h = (uint32_t*)(sm + S_W3H);
    uint32_t* W3l = (uint32_t*)(sm + S_W3L);
    uint32_t* Ahb[2] = { (uint32_t*)(sm + S_AH0), (uint32_t*)(sm + S_AH1) };
    uint32_t* Alb[2] = { (uint32_t*)(sm + S_AL0), (uint32_t*)(sm + S_AL1) };
    float* b1 = (float*)(sm + S_B1);
    float* b2 = (float*)(sm + S_B2);
    float* b3 = (float*)(sm + S_B3);
    int* sdstb[2] = { (int*)(sm + S_DST0), (int*)(sm + S_DST1) };
    int tid = threadIdx.x;

    stage_W(W1, W1h, W1l, 77, 44, tid, 128);
    stage_W(W2, W2h, W2l, 64, 36, tid, 128);
    stage_W(W3, W3h, W3l, 64, 36, tid, 128);
    if (tid < 64) { b1[tid] = B1[tid]; b2[tid] = B2[tid]; b3[tid] = B3[tid]; }
    __syncthreads();

    int lane = tid & 31, w = tid >> 5;
    int rowbase = w * 16;
    int g = lane >> 2, c2 = (lane & 3) * 2;
    int half = tid & 1, row = tid >> 1;
    const int str = gridDim.x;
    const int NT = (ES + 63) / 64;

    float4 st[10];
    float2 sp0 = make_float2(0.f, 0.f), sp1 = make_float2(0.f, 0.f);
    float sdis = 0.0f;
    int d_cur = 0, s_nx = 0, d_nx = 0;
    bool act_cur = false, act_nx = false;

    int t = blockIdx.x;
    if (t < NT) {
        int e = t * 64 + row; act_cur = e < ES; int ec = act_cur ? e : 0;
        int s0 = esrc[ec]; d_cur = edst[ec];
        s2s_load(half, s0, d_cur, ec, pos_state, xin, hbuf, edis, st, sp0, sp1, sdis);
    }
    {
        int tn = t + str;
        if (tn < NT) {
            int e = tn * 64 + row; act_nx = e < ES; int ec = act_nx ? e : 0;
            s_nx = esrc[ec]; d_nx = edst[ec];
        }
    }
    int p = 0;

    for (; t < NT; t += str) {
        uint32_t* Ahp = Ahb[p];
        uint32_t* Alp = Alb[p];
        s2s_store(half, row, Ahp, Alp, st, sp0, sp1, sdis);
        if (half == 0) {
            sdstb[p][row] = act_cur ? d_cur : -1;
            if (act_cur) atomicAdd(g_deg + d_cur, 1.0f);
        }
        __syncthreads();
        // prefetch next tile's data (lands during MMA below)
        int tn = t + str;
        if (tn < NT) {
            int e = tn * 64 + row; int ec = act_nx ? e : 0;
            s2s_load(half, s_nx, d_nx, ec, pos_state, xin, hbuf, edis, st, sp0, sp1, sdis);
        }
        // prefetch indices two tiles ahead
        int t2 = t + 2 * str;
        bool act2 = false; int s2v = 0, d2v = 0;
        if (t2 < NT) {
            int e = t2 * 64 + row; act2 = e < ES; int ec = act2 ? e : 0;
            s2v = esrc[ec]; d2v = edst[ec];
        }

        float acc[8][4];
        uint32_t zh[16], zl[16];
        layer_smem(acc, Ahp, Alp, 44, rowbase, W1h, W1l, 44, 5, lane);
        epi(acc, b1, zh, zl, lane);
        layer_regs(acc, zh, zl, W2h, W2l, lane);
        epi(acc, b2, zh, zl, lane);
        layer_regs(acc, zh, zl, W3h, W3l, lane);

        int* sd = sdstb[p];
        int d0 = sd[rowbase + g], d1 = sd[rowbase + g + 8];
#pragma unroll
        for (int nt2 = 0; nt2 < 8; nt2++) {
            int col = nt2 * 8 + c2;
            float2 b = *(const float2*)(b3 + col);
            if (d0 >= 0) red2(g_sum_x + (size_t)d0 * 64 + col, acc[nt2][0] + b.x, acc[nt2][1] + b.y);
            if (d1 >= 0) red2(g_sum_x + (size_t)d1 * 64 + col, acc[nt2][2] + b.x, acc[nt2][3] + b.y);
        }
        // rotate pipeline state
        act_cur = act_nx; d_cur = d_nx;
        act_nx = act2; s_nx = s2v; d_nx = d2v;
        p ^= 1;
    }
}

// ---------------------------------------------------------------------------
// a2s: 13->64->64->64. A/W1 stride 12 words, kchunks=1. Gather 2 threads/row.
#define A_W1H 0
#define A_W1L 3072
#define A_W2H 6144
#define A_W2L 15360
#define A_W3H 24576
#define A_W3L 33792
#define A_AH  43008
#define A_AL  46080
#define A_B1  49152
#define A_B2  49408
#define A_B3  49664
#define A_DST 49920
#define A2S_SMEM 50176

__global__ void __launch_bounds__(128, 2) a2s_kernel(
    const float* __restrict__ pos_state, const float* __restrict__ pos_action,
    const float* __restrict__ u,
    const int* __restrict__ esrc, const int* __restrict__ edst,
    const float* __restrict__ edis,
    const float* __restrict__ W1, const float* __restrict__ B1,
    const float* __restrict__ W2, const float* __restrict__ B2,
    const float* __restrict__ W3, const float* __restrict__ B3)
{
    extern __shared__ char sm[];
    uint32_t* W1h = (uint32_t*)(sm + A_W1H);
    uint32_t* W1l = (uint32_t*)(sm + A_W1L);
    uint32_t* W2h = (uint32_t*)(sm + A_W2H);
    uint32_t* W2l = (uint32_t*)(sm + A_W2L);
    uint32_t* W3h = (uint32_t*)(sm + A_W3H);
    uint32_t* W3l = (uint32_t*)(sm + A_W3L);
    uint32_t* Ah  = (uint32_t*)(sm + A_AH);
    uint32_t* Al  = (uint32_t*)(sm + A_AL);
    float* b1 = (float*)(sm + A_B1);
    float* b2 = (float*)(sm + A_B2);
    float* b3 = (float*)(sm + A_B3);
    int* sdst = (int*)(sm + A_DST);
    int tid = threadIdx.x;

    stage_W(W1, W1h, W1l, 13, 12, tid, 128);
    stage_W(W2, W2h, W2l, 64, 36, tid, 128);
    stage_W(W3, W3h, W3l, 64, 36, tid, 128);
    if (tid < 64) { b1[tid] = B1[tid]; b2[tid] = B2[tid]; b3[tid] = B3[tid]; }
    __syncthreads();

    int lane = tid & 31, w = tid >> 5;
    int rowbase = w * 16;
    int g = lane >> 2, c2 = (lane & 3) * 2;
    int half = tid & 1, row = tid >> 1;
    const int NT = (EA + 63) / 64;
    bool first = true;

    for (int t = blockIdx.x; t < NT; t += gridDim.x) {
        if (!first) __syncthreads();   // previous compute done before overwrite
        first = false;
        {
            int e = t * 64 + row;
            bool act = e < EA;
            int ec = act ? e : 0;
            int s = esrc[ec], d = edst[ec];
            uint32_t* rh = Ah + row * 12;
            uint32_t* rl = Al + row * 12;
            uint32_t hi, lo;
            const float4* u4 = (const float4*)(u + 8 * (size_t)s);
            if (half == 0) {
                float2 pa = *(const float2*)(pos_action + 2 * (size_t)s);
                float2 pd = *(const float2*)(pos_state + 2 * (size_t)d);
                float dis = edis[ec];
                float4 ua = u4[0];
                split2(pa.x, pa.y, hi, lo); rh[0] = hi; rl[0] = lo;
                split2(pd.x, pd.y, hi, lo); rh[1] = hi; rl[1] = lo;
                split2(dis, ua.x, hi, lo);  rh[2] = hi; rl[2] = lo;
                split2(ua.y, ua.z, hi, lo); rh[3] = hi; rl[3] = lo;
                sdst[row] = act ? d : -1;
            } else {
                float4 ua = u4[0], ub = u4[1];
                split2(ua.w, ub.x, hi, lo); rh[4] = hi; rl[4] = lo;
                split2(ub.y, ub.z, hi, lo); rh[5] = hi; rl[5] = lo;
                split2(ub.w, 0.0f, hi, lo); rh[6] = hi; rl[6] = lo;
                rh[7] = 0; rl[7] = 0;
            }
        }
        __syncthreads();

        float acc[8][4];
        uint32_t zh[16], zl[16];
        layer_smem(acc, Ah, Al, 12, rowbase, W1h, W1l, 12, 1, lane);
        epi(acc, b1, zh, zl, lane);
        layer_regs(acc, zh, zl, W2h, W2l, lane);
        epi(acc, b2, zh, zl, lane);
        layer_regs(acc, zh, zl, W3h, W3l, lane);

        int d0 = sdst[rowbase + g], d1 = sdst[rowbase + g + 8];
#pragma unroll
        for (int nt2 = 0; nt2 < 8; nt2++) {
            int col = nt2 * 8 + c2;
            float2 b = *(const float2*)(b3 + col);
            if (d0 >= 0) red2(g_sum_u + (size_t)d0 * 64 + col, acc[nt2][0] + b.x, acc[nt2][1] + b.y);
            if (d1 >= 0) red2(g_sum_u + (size_t)d1 * 64 + col, acc[nt2][2] + b.x, acc[nt2][3] + b.y);
        }
    }
}

// ---------------------------------------------------------------------------
// upd: 202->64->64->64. A/W1 stride 108 words, kchunks=13. Gather 2 threads/row.
#define U_W1H 0
#define U_W1L 27648
#define U_W2H 55296
#define U_W2L 64512
#define U_W3H 73728
#define U_W3L 82944
#define U_AH  92160
#define U_AL  119808
#define U_B1  147456
#define U_B2  147712
#define U_B3  147968
#define UPD_SMEM 148224

__global__ void __launch_bounds__(128, 1) upd_kernel(
    const float* __restrict__ pos_state, const float* __restrict__ hbuf,
    const float* __restrict__ xin,
    const float* __restrict__ W1, const float* __restrict__ B1,
    const float* __restrict__ W2, const float* __restrict__ B2,
    const float* __restrict__ W3, const float* __restrict__ B3,
    float* __restrict__ out)
{
    extern __shared__ char sm[];
    uint32_t* W1h = (uint32_t*)(sm + U_W1H);
    uint32_t* W1l = (uint32_t*)(sm + U_W1L);
    uint32_t* W2h = (uint32_t*)(sm + U_W2H);
    uint32_t* W2l = (uint32_t*)(sm + U_W2L);
    uint32_t* W3h = (uint32_t*)(sm + U_W3H);
    uint32_t* W3l = (uint32_t*)(sm + U_W3L);
    uint32_t* Ah  = (uint32_t*)(sm + U_AH);
    uint32_t* Al  = (uint32_t*)(sm + U_AL);
    float* b1 = (float*)(sm + U_B1);
    float* b2 = (float*)(sm + U_B2);
    float* b3 = (float*)(sm + U_B3);
    int tid = threadIdx.x;

    stage_W(W1, W1h, W1l, 202, 108, tid, 128);
    stage_W(W2, W2h, W2l, 64, 36, tid, 128);
    stage_W(W3, W3h, W3l, 64, 36, tid, 128);
    if (tid < 64) { b1[tid] = B1[tid]; b2[tid] = B2[tid]; b3[tid] = B3[tid]; }
    __syncthreads();

    int lane = tid & 31, w = tid >> 5;
    int rowbase = w * 16;
    int g = lane >> 2, c2 = (lane & 3) * 2;
    int half = tid & 1, row = tid >> 1;
    const int NT = (NS + 63) / 64;
    bool first = true;

    for (int t = blockIdx.x; t < NT; t += gridDim.x) {
        if (!first) __syncthreads();
        first = false;
        {
            int n = t * 64 + row;
            int nc = (n < NS) ? n : 0;
            uint32_t* rh = Ah + row * 108;
            uint32_t* rl = Al + row * 108;
            uint32_t hi, lo;
            if (half == 0) {
                // words 0..51: ps + h[0..63] + su[0..37]
                float2 ps = *(const float2*)(pos_state + 2 * (size_t)nc);
                split2(ps.x, ps.y, hi, lo); rh[0] = hi; rl[0] = lo;
                const float4* h4 = (const float4*)(hbuf + 64 * (size_t)nc);
#pragma unroll 4
                for (int i = 0; i < 16; i++) {
                    float4 v = h4[i];
                    split2(v.x, v.y, hi, lo); rh[1 + 2 * i] = hi; rl[1 + 2 * i] = lo;
                    split2(v.z, v.w, hi, lo); rh[2 + 2 * i] = hi; rl[2 + 2 * i] = lo;
                }
                const float4* su4 = (const float4*)(g_sum_u + 64 * (size_t)nc);
#pragma unroll 4
                for (int i = 0; i < 9; i++) {
                    float4 v = su4[i];
                    split2(v.x, v.y, hi, lo); rh[33 + 2 * i] = hi; rl[33 + 2 * i] = lo;
                    split2(v.z, v.w, hi, lo); rh[34 + 2 * i] = hi; rl[34 + 2 * i] = lo;
                }
                float4 v9 = su4[9];
                split2(v9.x, v9.y, hi, lo); rh[51] = hi; rl[51] = lo;
            } else {
                // words 52..103: su[38..63] + mx[0..63] + x[0..7] + pad
                const float4* su4 = (const float4*)(g_sum_u + 64 * (size_t)nc);
                float4 v9 = su4[9];
                split2(v9.z, v9.w, hi, lo); rh[52] = hi; rl[52] = lo;
#pragma unroll 2
                for (int i = 10; i < 16; i++) {
                    float4 v = su4[i];
                    split2(v.x, v.y, hi, lo); rh[33 + 2 * i] = hi; rl[33 + 2 * i] = lo;
                    split2(v.z, v.w, hi, lo); rh[34 + 2 * i] = hi; rl[34 + 2 * i] = lo;
                }
                float inv = rcp_fma(fmaxf(g_deg[nc], 1.0f));
                const float4* sx4 = (const float4*)(g_sum_x + 64 * (size_t)nc);
#pragma unroll 4
                for (int i = 0; i < 16; i++) {
                    float4 v = sx4[i];
                    split2(v.x * inv, v.y * inv, hi, lo); rh[65 + 2 * i] = hi; rl[65 + 2 * i] = lo;
                    split2(v.z * inv, v.w * inv, hi, lo); rh[66 + 2 * i] = hi; rl[66 + 2 * i] = lo;
                }
                const float4* x4 = (const float4*)(xin + 8 * (size_t)nc);
                float4 xa = x4[0], xb = x4[1];
                split2(xa.x, xa.y, hi, lo); rh[97] = hi;  rl[97] = lo;
                split2(xa.z, xa.w, hi, lo); rh[98] = hi;  rl[98] = lo;
                split2(xb.x, xb.y, hi, lo); rh[99] = hi;  rl[99] = lo;
                split2(xb.z, xb.w, hi, lo); rh[100] = hi; rl[100] = lo;
                rh[101] = 0; rl[101] = 0;
                rh[102] = 0; rl[102] = 0;
                rh[103] = 0; rl[103] = 0;
            }
        }
        __syncthreads();

        float acc[8][4];
        uint32_t zh[16], zl[16];
        layer_smem(acc, Ah, Al, 108, rowbase, W1h, W1l, 108, 13, lane);
        epi(acc, b1, zh, zl, lane);
        layer_regs(acc, zh, zl, W2h, W2l, lane);
        epi(acc, b2, zh, zl, lane);
        layer_regs(acc, zh, zl, W3h, W3l, lane);

        int n0 = t * 64 + rowbase + g;
        int n1 = n0 + 8;
#pragma unroll
        for (int nt2 = 0; nt2 < 8; nt2++) {
            int col = nt2 * 8 + c2;
            float2 b = *(const float2*)(b3 + col);
            if (n0 < NS)
                *(float2*)(out + (size_t)n0 * 64 + col) =
                    make_float2(acc[nt2][0] + b.x, acc[nt2][1] + b.y);
            if (n1 < NS)
                *(float2*)(out + (size_t)n1 * 64 + col) =
                    make_float2(acc[nt2][2] + b.x, acc[nt2][3] + b.y);
        }
    }
}

// ---------------------------------------------------------------------------
extern "C" void kernel_launch(void* const* d_in, const int* in_sizes, int n_in,
                              void* d_out, int out_size) {
    const float* pos_state  = (const float*)d_in[0];
    const float* pos_action = (const float*)d_in[1];
    const float* h          = (const float*)d_in[2];
    const float* x          = (const float*)d_in[3];
    const float* u          = (const float*)d_in[4];
    const int*   a2s_src    = (const int*)d_in[5];
    const int*   a2s_dst    = (const int*)d_in[6];
    const float* a2s_dis    = (const float*)d_in[7];
    const int*   s2s_src    = (const int*)d_in[8];
    const int*   s2s_dst    = (const int*)d_in[9];
    const float* s2s_dis    = (const float*)d_in[10];
    const float* u2h_w1 = (const float*)d_in[11];
    const float* u2h_b1 = (const float*)d_in[12];
    const float* u2h_w2 = (const float*)d_in[13];
    const float* u2h_b2 = (const float*)d_in[14];
    const float* u2h_w3 = (const float*)d_in[15];
    const float* u2h_b3 = (const float*)d_in[16];
    const float* x2h_w1 = (const float*)d_in[17];
    const float* x2h_b1 = (const float*)d_in[18];
    const float* x2h_w2 = (const float*)d_in[19];
    const float* x2h_b2 = (const float*)d_in[20];
    const float* x2h_w3 = (const float*)d_in[21];
    const float* x2h_b3 = (const float*)d_in[22];
    const float* upd_w1 = (const float*)d_in[23];
    const float* upd_b1 = (const float*)d_in[24];
    const float* upd_w2 = (const float*)d_in[25];
    const float* upd_b2 = (const float*)d_in[26];
    const float* upd_w3 = (const float*)d_in[27];
    const float* upd_b3 = (const float*)d_in[28];
    float* out = (float*)d_out;

    cudaFuncSetAttribute(s2s_kernel, cudaFuncAttributeMaxDynamicSharedMemorySize, S2S_SMEM);
    cudaFuncSetAttribute(a2s_kernel, cudaFuncAttributeMaxDynamicSharedMemorySize, A2S_SMEM);
    cudaFuncSetAttribute(upd_kernel, cudaFuncAttributeMaxDynamicSharedMemorySize, UPD_SMEM);

    zero_kernel<<<(NS * 64 + 255) / 256, 256>>>();

    a2s_kernel<<<444, 128, A2S_SMEM>>>(
        pos_state, pos_action, u, a2s_src, a2s_dst, a2s_dis,
        u2h_w1, u2h_b1, u2h_w2, u2h_b2, u2h_w3, u2h_b3);

    s2s_kernel<<<296, 128, S2S_SMEM>>>(
        pos_state, x, h, s2s_src, s2s_dst, s2s_dis,
        x2h_w1, x2h_b1, x2h_w2, x2h_b2, x2h_w3, x2h_b3);

    upd_kernel<<<148, 128, UPD_SMEM>>>(
        pos_state, h, x,
        upd_w1, upd_b1, upd_w2, upd_b2, upd_w3, upd_b3,
        out);
}

// round 15
// speedup vs baseline: 1.1909x; 1.1909x over previous
#include <cuda_runtime.h>
#include <cuda_bf16.h>
#include <stdint.h>

#define NS 50000
#define ES 1000000
#define EA 500000

// Scratch (allocation-free rule): device globals, 16B-aligned.
__device__ __align__(16) float g_sum_u[NS * 64];
__device__ __align__(16) float g_sum_x[NS * 64];
__device__ float g_deg[NS];

// ---------------------------------------------------------------------------
__device__ __forceinline__ float rcp_fma(float d) {
    float r = __int_as_float(0x7EF311C3 - __float_as_int(d));
    r = r * fmaf(-d, r, 2.0f);
    r = r * fmaf(-d, r, 2.0f);
    r = r * fmaf(-d, r, 2.0f);
    return r;
}
__device__ __forceinline__ float my_tanh(float v) {
    float x = fminf(fmaxf(v, -7.90531110f), 7.90531110f);
    float x2 = x * x;
    float p = -2.76076847742355e-16f;
    p = fmaf(p, x2, 2.00018790482477e-13f);
    p = fmaf(p, x2, -8.60467152213735e-11f);
    p = fmaf(p, x2, 5.12229709037114e-08f);
    p = fmaf(p, x2, 1.48572235717979e-05f);
    p = fmaf(p, x2, 6.37261928875436e-04f);
    p = fmaf(p, x2, 4.89352455891786e-03f);
    float q = 1.19825839466702e-06f;
    q = fmaf(q, x2, 1.18534705686654e-04f);
    q = fmaf(q, x2, 2.26843463243900e-03f);
    q = fmaf(q, x2, 4.89352518554385e-03f);
    return (x * p) * rcp_fma(q);
}
// split pair (a=even idx, b=odd idx) into bf16x2 hi/lo planes (low half = even)
__device__ __forceinline__ void split2(float a, float b, uint32_t& hi, uint32_t& lo) {
    __nv_bfloat16 ah = __float2bfloat16(a), bh = __float2bfloat16(b);
    float ar = a - __bfloat162float(ah), br = b - __bfloat162float(bh);
    __nv_bfloat16 al = __float2bfloat16(ar), bl = __float2bfloat16(br);
    hi = ((uint32_t)__bfloat16_as_ushort(bh) << 16) | (uint32_t)__bfloat16_as_ushort(ah);
    lo = ((uint32_t)__bfloat16_as_ushort(bl) << 16) | (uint32_t)__bfloat16_as_ushort(al);
}
__device__ __forceinline__ void mma_bf16(float c[4], uint32_t a0, uint32_t a1,
                                         uint32_t a2, uint32_t a3,
                                         uint32_t b0, uint32_t b1) {
    asm volatile("mma.sync.aligned.m16n8k16.row.col.f32.bf16.bf16.f32 "
        "{%0,%1,%2,%3}, {%4,%5,%6,%7}, {%8,%9}, {%0,%1,%2,%3};"
        : "+f"(c[0]), "+f"(c[1]), "+f"(c[2]), "+f"(c[3])
        : "r"(a0), "r"(a1), "r"(a2), "r"(a3), "r"(b0), "r"(b1));
}
__device__ __forceinline__ void red2(float* p, float a, float b) {
    asm volatile("red.global.add.v2.f32 [%0], {%1,%2};" :: "l"(p), "f"(a), "f"(b) : "memory");
}

// Stage W[k][64] -> Wt[n][kpad] (bf16 hi/lo words), row stride WSw words.
__device__ void stage_W(const float* __restrict__ W, uint32_t* wh, uint32_t* wl,
                        int Kin, int WSw, int tid, int nt) {
    for (int idx = tid; idx < 64 * WSw; idx += nt) {
        int n = idx / WSw, kw = idx % WSw;
        int k0 = kw * 2;
        float v0 = (k0 < Kin) ? W[(size_t)k0 * 64 + n] : 0.0f;
        float v1 = (k0 + 1 < Kin) ? W[(size_t)(k0 + 1) * 64 + n] : 0.0f;
        uint32_t hi, lo;
        split2(v0, v1, hi, lo);
        wh[idx] = hi; wl[idx] = lo;
    }
}

// Layer with A in smem (3-term bf16-split accumulate).
__device__ __forceinline__ void layer_smem(float acc[8][4],
    const uint32_t* Ah, const uint32_t* Al, int ASw, int rowbase,
    const uint32_t* Wh, const uint32_t* Wl, int WSw, int kchunks, int lane)
{
    int g = lane >> 2, c = lane & 3;
#pragma unroll
    for (int i = 0; i < 8; i++)
#pragma unroll
        for (int j = 0; j < 4; j++) acc[i][j] = 0.0f;
    const uint32_t* a0p = Ah + (rowbase + g) * ASw + c;
    const uint32_t* a1p = Ah + (rowbase + g + 8) * ASw + c;
    const uint32_t* l0p = Al + (rowbase + g) * ASw + c;
    const uint32_t* l1p = Al + (rowbase + g + 8) * ASw + c;
    for (int kc = 0; kc < kchunks; kc++) {
        uint32_t ah0 = a0p[kc * 8], ah1 = a1p[kc * 8];
        uint32_t ah2 = a0p[kc * 8 + 4], ah3 = a1p[kc * 8 + 4];
        uint32_t al0 = l0p[kc * 8], al1 = l1p[kc * 8];
        uint32_t al2 = l0p[kc * 8 + 4], al3 = l1p[kc * 8 + 4];
#pragma unroll
        for (int nt2 = 0; nt2 < 8; nt2++) {
            const uint32_t* bh = Wh + (nt2 * 8 + g) * WSw + kc * 8 + c;
            const uint32_t* bl = Wl + (nt2 * 8 + g) * WSw + kc * 8 + c;
            uint32_t bh0 = bh[0], bh1 = bh[4];
            uint32_t bl0 = bl[0], bl1 = bl[4];
            mma_bf16(acc[nt2], ah0, ah1, ah2, ah3, bh0, bh1);
            mma_bf16(acc[nt2], ah0, ah1, ah2, ah3, bl0, bl1);
            mma_bf16(acc[nt2], al0, al1, al2, al3, bh0, bh1);
        }
    }
}

// Layer with activations in registers (C-frag == A-frag layout), K=64 (4 chunks).
__device__ __forceinline__ void layer_regs(float acc[8][4],
    const uint32_t zh[16], const uint32_t zl[16],
    const uint32_t* Wh, const uint32_t* Wl, int lane)   // WSw = 36
{
    int g = lane >> 2, c = lane & 3;
#pragma unroll
    for (int i = 0; i < 8; i++)
#pragma unroll
        for (int j = 0; j < 4; j++) acc[i][j] = 0.0f;
#pragma unroll
    for (int kc = 0; kc < 4; kc++) {
        uint32_t ah0 = zh[4 * kc + 0], ah1 = zh[4 * kc + 1];
        uint32_t ah2 = zh[4 * kc + 2], ah3 = zh[4 * kc + 3];
        uint32_t al0 = zl[4 * kc + 0], al1 = zl[4 * kc + 1];
        uint32_t al2 = zl[4 * kc + 2], al3 = zl[4 * kc + 3];
#pragma unroll
        for (int nt2 = 0; nt2 < 8; nt2++) {
            const uint32_t* bh = Wh + (nt2 * 8 + g) * 36 + kc * 8 + c;
            const uint32_t* bl = Wl + (nt2 * 8 + g) * 36 + kc * 8 + c;
            uint32_t bh0 = bh[0], bh1 = bh[4];
            uint32_t bl0 = bl[0], bl1 = bl[4];
            mma_bf16(acc[nt2], ah0, ah1, ah2, ah3, bh0, bh1);
            mma_bf16(acc[nt2], ah0, ah1, ah2, ah3, bl0, bl1);
            mma_bf16(acc[nt2], al0, al1, al2, al3, bh0, bh1);
        }
    }
}

// bias + tanh + bf16-split pack: acc -> next-layer A-frags (registers).
__device__ __forceinline__ void epi(const float acc[8][4], const float* bias,
                                    uint32_t zh[16], uint32_t zl[16], int lane)
{
    int c2 = (lane & 3) * 2;
#pragma unroll
    for (int nt2 = 0; nt2 < 8; nt2++) {
        float2 b = *(const float2*)(bias + nt2 * 8 + c2);
        float t0 = my_tanh(acc[nt2][0] + b.x);
        float t1 = my_tanh(acc[nt2][1] + b.y);
        float t2 = my_tanh(acc[nt2][2] + b.x);
        float t3 = my_tanh(acc[nt2][3] + b.y);
        split2(t0, t1, zh[2 * nt2 + 0], zl[2 * nt2 + 0]);
        split2(t2, t3, zh[2 * nt2 + 1], zl[2 * nt2 + 1]);
    }
}

// ---------------------------------------------------------------------------
__global__ void zero_kernel(void) {
    int i = blockIdx.x * blockDim.x + threadIdx.x;
    if (i < NS * 64) { g_sum_u[i] = 0.0f; g_sum_x[i] = 0.0f; }
    if (i < NS) g_deg[i] = 0.0f;
}

// ---------------------------------------------------------------------------
// s2s: 77->64->64->64. 256 threads, 128 edges/tile (8 warps x 16 edges).
// A stride 44 words, W1 stride 44, kchunks=5. Gather 2 threads/row.
#define S_W1H 0
#define S_W1L 11264
#define S_W2H 22528
#define S_W2L 31744
#define S_W3H 40960
#define S_W3L 50176
#define S_AH  59392
#define S_AL  81920
#define S_B1  104448
#define S_B2  104704
#define S_B3  104960
#define S_DST 105216
#define S2S_SMEM 105728

__global__ void __launch_bounds__(256, 2) s2s_kernel(
    const float* __restrict__ pos_state, const float* __restrict__ xin,
    const float* __restrict__ hbuf,
    const int* __restrict__ esrc, const int* __restrict__ edst,
    const float* __restrict__ edis,
    const float* __restrict__ W1, const float* __restrict__ B1,
    const float* __restrict__ W2, const float* __restrict__ B2,
    const float* __restrict__ W3, const float* __restrict__ B3)
{
    extern __shared__ char sm[];
    uint32_t* W1h = (uint32_t*)(sm + S_W1H);
    uint32_t* W1l = (uint32_t*)(sm + S_W1L);
    uint32_t* W2h = (uint32_t*)(sm + S_W2H);
    uint32_t* W2l = (uint32_t*)(sm + S_W2L);
    uint32_t* W3h = (uint32_t*)(sm + S_W3H);
    uint32_t* W3l = (uint32_t*)(sm + S_W3L);
    uint32_t* Ah  = (uint32_t*)(sm + S_AH);
    uint32_t* Al  = (uint32_t*)(sm + S_AL);
    float* b1 = (float*)(sm + S_B1);
    float* b2 = (float*)(sm + S_B2);
    float* b3 = (float*)(sm + S_B3);
    int* sdst = (int*)(sm + S_DST);
    int tid = threadIdx.x;

    stage_W(W1, W1h, W1l, 77, 44, tid, 256);
    stage_W(W2, W2h, W2l, 64, 36, tid, 256);
    stage_W(W3, W3h, W3l, 64, 36, tid, 256);
    if (tid < 64) { b1[tid] = B1[tid]; b2[tid] = B2[tid]; b3[tid] = B3[tid]; }
    __syncthreads();

    int lane = tid & 31, w = tid >> 5;
    int rowbase = w * 16;
    int g = lane >> 2, c2 = (lane & 3) * 2;
    int half = tid & 1, row = tid >> 1;
    const int NT = (ES + 127) / 128;
    bool first = true;

    for (int t = blockIdx.x; t < NT; t += gridDim.x) {
        if (!first) __syncthreads();
        first = false;
        {
            int e = t * 128 + row;
            bool act = e < ES;
            int ec = act ? e : 0;
            int s = esrc[ec], d = edst[ec];
            uint32_t* rh = Ah + row * 44;
            uint32_t* rl = Al + row * 44;
            uint32_t hi, lo;
            const float4* h4 = (const float4*)(hbuf + 64 * (size_t)s);
            if (half == 0) {
                // words 0..19: ps, pd, dis, x[0..7], h[0..27]
                float2 ps = *(const float2*)(pos_state + 2 * (size_t)s);
                float2 pd = *(const float2*)(pos_state + 2 * (size_t)d);
                float dis = edis[ec];
                const float4* x4 = (const float4*)(xin + 8 * (size_t)s);
                float4 xa = x4[0], xb = x4[1];
                split2(ps.x, ps.y, hi, lo); rh[0] = hi; rl[0] = lo;
                split2(pd.x, pd.y, hi, lo); rh[1] = hi; rl[1] = lo;
                split2(dis, xa.x, hi, lo);  rh[2] = hi; rl[2] = lo;
                split2(xa.y, xa.z, hi, lo); rh[3] = hi; rl[3] = lo;
                split2(xa.w, xb.x, hi, lo); rh[4] = hi; rl[4] = lo;
                split2(xb.y, xb.z, hi, lo); rh[5] = hi; rl[5] = lo;
                float prev = xb.w;
#pragma unroll
                for (int i = 0; i < 7; i++) {
                    float4 f = h4[i];
                    split2(prev, f.x, hi, lo); rh[6 + 2 * i] = hi; rl[6 + 2 * i] = lo;
                    split2(f.y, f.z, hi, lo);  rh[7 + 2 * i] = hi; rl[7 + 2 * i] = lo;
                    prev = f.w;
                }
                sdst[row] = act ? d : -1;
                if (act) atomicAdd(g_deg + d, 1.0f);
            } else {
                // words 20..39: h[27..63] + pad
                float4 f6 = h4[6];
                float prev = f6.w;  // h[27]
#pragma unroll
                for (int i = 7; i < 16; i++) {
                    float4 f = h4[i];
                    split2(prev, f.x, hi, lo); rh[6 + 2 * i] = hi; rl[6 + 2 * i] = lo;
                    split2(f.y, f.z, hi, lo);  rh[7 + 2 * i] = hi; rl[7 + 2 * i] = lo;
                    prev = f.w;
                }
                split2(prev, 0.0f, hi, lo); rh[38] = hi; rl[38] = lo;
                rh[39] = 0; rl[39] = 0;
            }
        }
        __syncthreads();

        float acc[8][4];
        uint32_t zh[16], zl[16];
        layer_smem(acc, Ah, Al, 44, rowbase, W1h, W1l, 44, 5, lane);
        epi(acc, b1, zh, zl, lane);
        layer_regs(acc, zh, zl, W2h, W2l, lane);
        epi(acc, b2, zh, zl, lane);
        layer_regs(acc, zh, zl, W3h, W3l, lane);

        int d0 = sdst[rowbase + g], d1 = sdst[rowbase + g + 8];
#pragma unroll
        for (int nt2 = 0; nt2 < 8; nt2++) {
            int col = nt2 * 8 + c2;
            float2 b = *(const float2*)(b3 + col);
            if (d0 >= 0) red2(g_sum_x + (size_t)d0 * 64 + col, acc[nt2][0] + b.x, acc[nt2][1] + b.y);
            if (d1 >= 0) red2(g_sum_x + (size_t)d1 * 64 + col, acc[nt2][2] + b.x, acc[nt2][3] + b.y);
        }
    }
}

// ---------------------------------------------------------------------------
// a2s: 13->64->64->64. 256 threads, 128 edges/tile. A/W1 stride 12, kchunks=1.
#define A_W1H 0
#define A_W1L 3072
#define A_W2H 6144
#define A_W2L 15360
#define A_W3H 24576
#define A_W3L 33792
#define A_AH  43008
#define A_AL  49152
#define A_B1  55296
#define A_B2  55552
#define A_B3  55808
#define A_DST 56064
#define A2S_SMEM 56576

__global__ void __launch_bounds__(256, 2) a2s_kernel(
    const float* __restrict__ pos_state, const float* __restrict__ pos_action,
    const float* __restrict__ u,
    const int* __restrict__ esrc, const int* __restrict__ edst,
    const float* __restrict__ edis,
    const float* __restrict__ W1, const float* __restrict__ B1,
    const float* __restrict__ W2, const float* __restrict__ B2,
    const float* __restrict__ W3, const float* __restrict__ B3)
{
    extern __shared__ char sm[];
    uint32_t* W1h = (uint32_t*)(sm + A_W1H);
    uint32_t* W1l = (uint32_t*)(sm + A_W1L);
    uint32_t* W2h = (uint32_t*)(sm + A_W2H);
    uint32_t* W2l = (uint32_t*)(sm + A_W2L);
    uint32_t* W3h = (uint32_t*)(sm + A_W3H);
    uint32_t* W3l = (uint32_t*)(sm + A_W3L);
    uint32_t* Ah  = (uint32_t*)(sm + A_AH);
    uint32_t* Al  = (uint32_t*)(sm + A_AL);
    float* b1 = (float*)(sm + A_B1);
    float* b2 = (float*)(sm + A_B2);
    float* b3 = (float*)(sm + A_B3);
    int* sdst = (int*)(sm + A_DST);
    int tid = threadIdx.x;

    stage_W(W1, W1h, W1l, 13, 12, tid, 256);
    stage_W(W2, W2h, W2l, 64, 36, tid, 256);
    stage_W(W3, W3h, W3l, 64, 36, tid, 256);
    if (tid < 64) { b1[tid] = B1[tid]; b2[tid] = B2[tid]; b3[tid] = B3[tid]; }
    __syncthreads();

    int lane = tid & 31, w = tid >> 5;
    int rowbase = w * 16;
    int g = lane >> 2, c2 = (lane & 3) * 2;
    int half = tid & 1, row = tid >> 1;
    const int NT = (EA + 127) / 128;
    bool first = true;

    for (int t = blockIdx.x; t < NT; t += gridDim.x) {
        if (!first) __syncthreads();
        first = false;
        {
            int e = t * 128 + row;
            bool act = e < EA;
            int ec = act ? e : 0;
            int s = esrc[ec], d = edst[ec];
            uint32_t* rh = Ah + row * 12;
            uint32_t* rl = Al + row * 12;
            uint32_t hi, lo;
            const float4* u4 = (const float4*)(u + 8 * (size_t)s);
            if (half == 0) {
                float2 pa = *(const float2*)(pos_action + 2 * (size_t)s);
                float2 pd = *(const float2*)(pos_state + 2 * (size_t)d);
                float dis = edis[ec];
                float4 ua = u4[0];
                split2(pa.x, pa.y, hi, lo); rh[0] = hi; rl[0] = lo;
                split2(pd.x, pd.y, hi, lo); rh[1] = hi; rl[1] = lo;
                split2(dis, ua.x, hi, lo);  rh[2] = hi; rl[2] = lo;
                split2(ua.y, ua.z, hi, lo); rh[3] = hi; rl[3] = lo;
                sdst[row] = act ? d : -1;
            } else {
                float4 ua = u4[0], ub = u4[1];
                split2(ua.w, ub.x, hi, lo); rh[4] = hi; rl[4] = lo;
                split2(ub.y, ub.z, hi, lo); rh[5] = hi; rl[5] = lo;
                split2(ub.w, 0.0f, hi, lo); rh[6] = hi; rl[6] = lo;
                rh[7] = 0; rl[7] = 0;
            }
        }
        __syncthreads();

        float acc[8][4];
        uint32_t zh[16], zl[16];
        layer_smem(acc, Ah, Al, 12, rowbase, W1h, W1l, 12, 1, lane);
        epi(acc, b1, zh, zl, lane);
        layer_regs(acc, zh, zl, W2h, W2l, lane);
        epi(acc, b2, zh, zl, lane);
        layer_regs(acc, zh, zl, W3h, W3l, lane);

        int d0 = sdst[rowbase + g], d1 = sdst[rowbase + g + 8];
#pragma unroll
        for (int nt2 = 0; nt2 < 8; nt2++) {
            int col = nt2 * 8 + c2;
            float2 b = *(const float2*)(b3 + col);
            if (d0 >= 0) red2(g_sum_u + (size_t)d0 * 64 + col, acc[nt2][0] + b.x, acc[nt2][1] + b.y);
            if (d1 >= 0) red2(g_sum_u + (size_t)d1 * 64 + col, acc[nt2][2] + b.x, acc[nt2][3] + b.y);
        }
    }
}

// ---------------------------------------------------------------------------
// upd: 202->64->64->64. 256 threads, 128 nodes/tile. A/W1 stride 108, kchunks=13.
#define U_W1H 0
#define U_W1L 27648
#define U_W2H 55296
#define U_W2L 64512
#define U_W3H 73728
#define U_W3L 82944
#define U_AH  92160
#define U_AL  147456
#define U_B1  202752
#define U_B2  203008
#define U_B3  203264
#define UPD_SMEM 203520

__global__ void __launch_bounds__(256, 1) upd_kernel(
    const float* __restrict__ pos_state, const float* __restrict__ hbuf,
    const float* __restrict__ xin,
    const float* __restrict__ W1, const float* __restrict__ B1,
    const float* __restrict__ W2, const float* __restrict__ B2,
    const float* __restrict__ W3, const float* __restrict__ B3,
    float* __restrict__ out)
{
    extern __shared__ char sm[];
    uint32_t* W1h = (uint32_t*)(sm + U_W1H);
    uint32_t* W1l = (uint32_t*)(sm + U_W1L);
    uint32_t* W2h = (uint32_t*)(sm + U_W2H);
    uint32_t* W2l = (uint32_t*)(sm + U_W2L);
    uint32_t* W3h = (uint32_t*)(sm + U_W3H);
    uint32_t* W3l = (uint32_t*)(sm + U_W3L);
    uint32_t* Ah  = (uint32_t*)(sm + U_AH);
    uint32_t* Al  = (uint32_t*)(sm + U_AL);
    float* b1 = (float*)(sm + U_B1);
    float* b2 = (float*)(sm + U_B2);
    float* b3 = (float*)(sm + U_B3);
    int tid = threadIdx.x;

    stage_W(W1, W1h, W1l, 202, 108, tid, 256);
    stage_W(W2, W2h, W2l, 64, 36, tid, 256);
    stage_W(W3, W3h, W3l, 64, 36, tid, 256);
    if (tid < 64) { b1[tid] = B1[tid]; b2[tid] = B2[tid]; b3[tid] = B3[tid]; }
    __syncthreads();

    int lane = tid & 31, w = tid >> 5;
    int rowbase = w * 16;
    int g = lane >> 2, c2 = (lane & 3) * 2;
    int half = tid & 1, row = tid >> 1;
    const int NT = (NS + 127) / 128;
    bool first = true;

    for (int t = blockIdx.x; t < NT; t += gridDim.x) {
        if (!first) __syncthreads();
        first = false;
        {
            int n = t * 128 + row;
            int nc = (n < NS) ? n : 0;
            uint32_t* rh = Ah + row * 108;
            uint32_t* rl = Al + row * 108;
            uint32_t hi, lo;
            if (half == 0) {
                // words 0..51: ps + h[0..63] + su[0..37]
                float2 ps = *(const float2*)(pos_state + 2 * (size_t)nc);
                split2(ps.x, ps.y, hi, lo); rh[0] = hi; rl[0] = lo;
                const float4* h4 = (const float4*)(hbuf + 64 * (size_t)nc);
#pragma unroll 4
                for (int i = 0; i < 16; i++) {
                    float4 v = h4[i];
                    split2(v.x, v.y, hi, lo); rh[1 + 2 * i] = hi; rl[1 + 2 * i] = lo;
                    split2(v.z, v.w, hi, lo); rh[2 + 2 * i] = hi; rl[2 + 2 * i] = lo;
                }
                const float4* su4 = (const float4*)(g_sum_u + 64 * (size_t)nc);
#pragma unroll 4
                for (int i = 0; i < 9; i++) {
                    float4 v = su4[i];
                    split2(v.x, v.y, hi, lo); rh[33 + 2 * i] = hi; rl[33 + 2 * i] = lo;
                    split2(v.z, v.w, hi, lo); rh[34 + 2 * i] = hi; rl[34 + 2 * i] = lo;
                }
                float4 v9 = su4[9];
                split2(v9.x, v9.y, hi, lo); rh[51] = hi; rl[51] = lo;
            } else {
                // words 52..103: su[38..63] + mx[0..63] + x[0..7] + pad
                const float4* su4 = (const float4*)(g_sum_u + 64 * (size_t)nc);
                float4 v9 = su4[9];
                split2(v9.z, v9.w, hi, lo); rh[52] = hi; rl[52] = lo;
#pragma unroll 2
                for (int i = 10; i < 16; i++) {
                    float4 v = su4[i];
                    split2(v.x, v.y, hi, lo); rh[33 + 2 * i] = hi; rl[33 + 2 * i] = lo;
                    split2(v.z, v.w, hi, lo); rh[34 + 2 * i] = hi; rl[34 + 2 * i] = lo;
                }
                float inv = rcp_fma(fmaxf(g_deg[nc], 1.0f));
                const float4* sx4 = (const float4*)(g_sum_x + 64 * (size_t)nc);
#pragma unroll 4
                for (int i = 0; i < 16; i++) {
                    float4 v = sx4[i];
                    split2(v.x * inv, v.y * inv, hi, lo); rh[65 + 2 * i] = hi; rl[65 + 2 * i] = lo;
                    split2(v.z * inv, v.w * inv, hi, lo); rh[66 + 2 * i] = hi; rl[66 + 2 * i] = lo;
                }
                const float4* x4 = (const float4*)(xin + 8 * (size_t)nc);
                float4 xa = x4[0], xb = x4[1];
                split2(xa.x, xa.y, hi, lo); rh[97] = hi;  rl[97] = lo;
                split2(xa.z, xa.w, hi, lo); rh[98] = hi;  rl[98] = lo;
                split2(xb.x, xb.y, hi, lo); rh[99] = hi;  rl[99] = lo;
                split2(xb.z, xb.w, hi, lo); rh[100] = hi; rl[100] = lo;
                rh[101] = 0; rl[101] = 0;
                rh[102] = 0; rl[102] = 0;
                rh[103] = 0; rl[103] = 0;
            }
        }
        __syncthreads();

        float acc[8][4];
        uint32_t zh[16], zl[16];
        layer_smem(acc, Ah, Al, 108, rowbase, W1h, W1l, 108, 13, lane);
        epi(acc, b1, zh, zl, lane);
        layer_regs(acc, zh, zl, W2h, W2l, lane);
        epi(acc, b2, zh, zl, lane);
        layer_regs(acc, zh, zl, W3h, W3l, lane);

        int n0 = t * 128 + rowbase + g;
        int n1 = n0 + 8;
#pragma unroll
        for (int nt2 = 0; nt2 < 8; nt2++) {
            int col = nt2 * 8 + c2;
            float2 b = *(const float2*)(b3 + col);
            if (n0 < NS)
                *(float2*)(out + (size_t)n0 * 64 + col) =
                    make_float2(acc[nt2][0] + b.x, acc[nt2][1] + b.y);
            if (n1 < NS)
                *(float2*)(out + (size_t)n1 * 64 + col) =
                    make_float2(acc[nt2][2] + b.x, acc[nt2][3] + b.y);
        }
    }
}

// ---------------------------------------------------------------------------
extern "C" void kernel_launch(void* const* d_in, const int* in_sizes, int n_in,
                              void* d_out, int out_size) {
    const float* pos_state  = (const float*)d_in[0];
    const float* pos_action = (const float*)d_in[1];
    const float* h          = (const float*)d_in[2];
    const float* x          = (const float*)d_in[3];
    const float* u          = (const float*)d_in[4];
    const int*   a2s_src    = (const int*)d_in[5];
    const int*   a2s_dst    = (const int*)d_in[6];
    const float* a2s_dis    = (const float*)d_in[7];
    const int*   s2s_src    = (const int*)d_in[8];
    const int*   s2s_dst    = (const int*)d_in[9];
    const float* s2s_dis    = (const float*)d_in[10];
    const float* u2h_w1 = (const float*)d_in[11];
    const float* u2h_b1 = (const float*)d_in[12];
    const float* u2h_w2 = (const float*)d_in[13];
    const float* u2h_b2 = (const float*)d_in[14];
    const float* u2h_w3 = (const float*)d_in[15];
    const float* u2h_b3 = (const float*)d_in[16];
    const float* x2h_w1 = (const float*)d_in[17];
    const float* x2h_b1 = (const float*)d_in[18];
    const float* x2h_w2 = (const float*)d_in[19];
    const float* x2h_b2 = (const float*)d_in[20];
    const float* x2h_w3 = (const float*)d_in[21];
    const float* x2h_b3 = (const float*)d_in[22];
    const float* upd_w1 = (const float*)d_in[23];
    const float* upd_b1 = (const float*)d_in[24];
    const float* upd_w2 = (const float*)d_in[25];
    const float* upd_b2 = (const float*)d_in[26];
    const float* upd_w3 = (const float*)d_in[27];
    const float* upd_b3 = (const float*)d_in[28];
    float* out = (float*)d_out;

    cudaFuncSetAttribute(s2s_kernel, cudaFuncAttributeMaxDynamicSharedMemorySize, S2S_SMEM);
    cudaFuncSetAttribute(a2s_kernel, cudaFuncAttributeMaxDynamicSharedMemorySize, A2S_SMEM);
    cudaFuncSetAttribute(upd_kernel, cudaFuncAttributeMaxDynamicSharedMemorySize, UPD_SMEM);

    zero_kernel<<<(NS * 64 + 255) / 256, 256>>>();

    a2s_kernel<<<296, 256, A2S_SMEM>>>(
        pos_state, pos_action, u, a2s_src, a2s_dst, a2s_dis,
        u2h_w1, u2h_b1, u2h_w2, u2h_b2, u2h_w3, u2h_b3);

    s2s_kernel<<<296, 256, S2S_SMEM>>>(
        pos_state, x, h, s2s_src, s2s_dst, s2s_dis,
        x2h_w1, x2h_b1, x2h_w2, x2h_b2, x2h_w3, x2h_b3);

    upd_kernel<<<148, 256, UPD_SMEM>>>(
        pos_state, h, x,
        upd_w1, upd_b1, upd_w2, upd_b2, upd_w3, upd_b3,
        out);
}

// round 16
// speedup vs baseline: 1.2194x; 1.0240x over previous
#include <cuda_runtime.h>
#include <cuda_bf16.h>
#include <stdint.h>

#define NS 50000
#define ES 1000000
#define EA 500000

// Scratch (allocation-free rule): device globals, 16B-aligned.
__device__ __align__(16) float g_sum_u[NS * 64];
__device__ __align__(16) float g_sum_x[NS * 64];
__device__ float g_deg[NS];

// ---------------------------------------------------------------------------
__device__ __forceinline__ float rcp_fma(float d) {
    float r = __int_as_float(0x7EF311C3 - __float_as_int(d));
    r = r * fmaf(-d, r, 2.0f);
    r = r * fmaf(-d, r, 2.0f);
    r = r * fmaf(-d, r, 2.0f);
    return r;
}
__device__ __forceinline__ float my_tanh(float v) {
    float x = fminf(fmaxf(v, -7.90531110f), 7.90531110f);
    float x2 = x * x;
    float p = -2.76076847742355e-16f;
    p = fmaf(p, x2, 2.00018790482477e-13f);
    p = fmaf(p, x2, -8.60467152213735e-11f);
    p = fmaf(p, x2, 5.12229709037114e-08f);
    p = fmaf(p, x2, 1.48572235717979e-05f);
    p = fmaf(p, x2, 6.37261928875436e-04f);
    p = fmaf(p, x2, 4.89352455891786e-03f);
    float q = 1.19825839466702e-06f;
    q = fmaf(q, x2, 1.18534705686654e-04f);
    q = fmaf(q, x2, 2.26843463243900e-03f);
    q = fmaf(q, x2, 4.89352518554385e-03f);
    return (x * p) * rcp_fma(q);
}
// split pair (a=even idx, b=odd idx) into bf16x2 hi/lo planes (low half = even)
__device__ __forceinline__ void split2(float a, float b, uint32_t& hi, uint32_t& lo) {
    __nv_bfloat16 ah = __float2bfloat16(a), bh = __float2bfloat16(b);
    float ar = a - __bfloat162float(ah), br = b - __bfloat162float(bh);
    __nv_bfloat16 al = __float2bfloat16(ar), bl = __float2bfloat16(br);
    hi = ((uint32_t)__bfloat16_as_ushort(bh) << 16) | (uint32_t)__bfloat16_as_ushort(ah);
    lo = ((uint32_t)__bfloat16_as_ushort(bl) << 16) | (uint32_t)__bfloat16_as_ushort(al);
}
__device__ __forceinline__ void mma_bf16(float c[4], uint32_t a0, uint32_t a1,
                                         uint32_t a2, uint32_t a3,
                                         uint32_t b0, uint32_t b1) {
    asm volatile("mma.sync.aligned.m16n8k16.row.col.f32.bf16.bf16.f32 "
        "{%0,%1,%2,%3}, {%4,%5,%6,%7}, {%8,%9}, {%0,%1,%2,%3};"
        : "+f"(c[0]), "+f"(c[1]), "+f"(c[2]), "+f"(c[3])
        : "r"(a0), "r"(a1), "r"(a2), "r"(a3), "r"(b0), "r"(b1));
}
__device__ __forceinline__ void red4(float* p, float a, float b, float c, float d) {
    asm volatile("red.global.add.v4.f32 [%0], {%1,%2,%3,%4};"
                 :: "l"(p), "f"(a), "f"(b), "f"(c), "f"(d) : "memory");
}

// Final-layer output-column permutation: true col T stored at smem row L(T)
// so each thread's accumulators form 4 consecutive output columns.
__device__ __forceinline__ int perm_L(int n) {
    int j = n >> 4, w = n & 1, p = (n >> 1) & 1, c2 = ((n >> 2) & 3) * 2;
    return (2 * j + p) * 8 + c2 + w;
}

// Stage W[k][64] -> Wt[n][kpad] (bf16 hi/lo words), row stride WSw words.
// perm: apply final-layer output permutation to the n (row) placement.
__device__ void stage_W(const float* __restrict__ W, uint32_t* wh, uint32_t* wl,
                        int Kin, int WSw, int tid, int nt, int perm) {
    for (int idx = tid; idx < 64 * WSw; idx += nt) {
        int n = idx / WSw, kw = idx % WSw;
        int k0 = kw * 2;
        float v0 = (k0 < Kin) ? W[(size_t)k0 * 64 + n] : 0.0f;
        float v1 = (k0 + 1 < Kin) ? W[(size_t)(k0 + 1) * 64 + n] : 0.0f;
        uint32_t hi, lo;
        split2(v0, v1, hi, lo);
        int r = perm ? perm_L(n) : n;
        wh[r * WSw + kw] = hi; wl[r * WSw + kw] = lo;
    }
}

// Layer with A in smem (3-term bf16-split accumulate).
__device__ __forceinline__ void layer_smem(float acc[8][4],
    const uint32_t* Ah, const uint32_t* Al, int ASw, int rowbase,
    const uint32_t* Wh, const uint32_t* Wl, int WSw, int kchunks, int lane)
{
    int g = lane >> 2, c = lane & 3;
#pragma unroll
    for (int i = 0; i < 8; i++)
#pragma unroll
        for (int j = 0; j < 4; j++) acc[i][j] = 0.0f;
    const uint32_t* a0p = Ah + (rowbase + g) * ASw + c;
    const uint32_t* a1p = Ah + (rowbase + g + 8) * ASw + c;
    const uint32_t* l0p = Al + (rowbase + g) * ASw + c;
    const uint32_t* l1p = Al + (rowbase + g + 8) * ASw + c;
    for (int kc = 0; kc < kchunks; kc++) {
        uint32_t ah0 = a0p[kc * 8], ah1 = a1p[kc * 8];
        uint32_t ah2 = a0p[kc * 8 + 4], ah3 = a1p[kc * 8 + 4];
        uint32_t al0 = l0p[kc * 8], al1 = l1p[kc * 8];
        uint32_t al2 = l0p[kc * 8 + 4], al3 = l1p[kc * 8 + 4];
#pragma unroll
        for (int nt2 = 0; nt2 < 8; nt2++) {
            const uint32_t* bh = Wh + (nt2 * 8 + g) * WSw + kc * 8 + c;
            const uint32_t* bl = Wl + (nt2 * 8 + g) * WSw + kc * 8 + c;
            uint32_t bh0 = bh[0], bh1 = bh[4];
            uint32_t bl0 = bl[0], bl1 = bl[4];
            mma_bf16(acc[nt2], ah0, ah1, ah2, ah3, bh0, bh1);
            mma_bf16(acc[nt2], ah0, ah1, ah2, ah3, bl0, bl1);
            mma_bf16(acc[nt2], al0, al1, al2, al3, bh0, bh1);
        }
    }
}

// Layer with activations in registers (C-frag == A-frag layout), K=64 (4 chunks).
__device__ __forceinline__ void layer_regs(float acc[8][4],
    const uint32_t zh[16], const uint32_t zl[16],
    const uint32_t* Wh, const uint32_t* Wl, int lane)   // WSw = 36
{
    int g = lane >> 2, c = lane & 3;
#pragma unroll
    for (int i = 0; i < 8; i++)
#pragma unroll
        for (int j = 0; j < 4; j++) acc[i][j] = 0.0f;
#pragma unroll
    for (int kc = 0; kc < 4; kc++) {
        uint32_t ah0 = zh[4 * kc + 0], ah1 = zh[4 * kc + 1];
        uint32_t ah2 = zh[4 * kc + 2], ah3 = zh[4 * kc + 3];
        uint32_t al0 = zl[4 * kc + 0], al1 = zl[4 * kc + 1];
        uint32_t al2 = zl[4 * kc + 2], al3 = zl[4 * kc + 3];
#pragma unroll
        for (int nt2 = 0; nt2 < 8; nt2++) {
            const uint32_t* bh = Wh + (nt2 * 8 + g) * 36 + kc * 8 + c;
            const uint32_t* bl = Wl + (nt2 * 8 + g) * 36 + kc * 8 + c;
            uint32_t bh0 = bh[0], bh1 = bh[4];
            uint32_t bl0 = bl[0], bl1 = bl[4];
            mma_bf16(acc[nt2], ah0, ah1, ah2, ah3, bh0, bh1);
            mma_bf16(acc[nt2], ah0, ah1, ah2, ah3, bl0, bl1);
            mma_bf16(acc[nt2], al0, al1, al2, al3, bh0, bh1);
        }
    }
}

// bias + tanh + bf16-split pack: acc -> next-layer A-frags (registers).
__device__ __forceinline__ void epi(const float acc[8][4], const float* bias,
                                    uint32_t zh[16], uint32_t zl[16], int lane)
{
    int c2 = (lane & 3) * 2;
#pragma unroll
    for (int nt2 = 0; nt2 < 8; nt2++) {
        float2 b = *(const float2*)(bias + nt2 * 8 + c2);
        float t0 = my_tanh(acc[nt2][0] + b.x);
        float t1 = my_tanh(acc[nt2][1] + b.y);
        float t2 = my_tanh(acc[nt2][2] + b.x);
        float t3 = my_tanh(acc[nt2][3] + b.y);
        split2(t0, t1, zh[2 * nt2 + 0], zl[2 * nt2 + 0]);
        split2(t2, t3, zh[2 * nt2 + 1], zl[2 * nt2 + 1]);
    }
}

// Permuted-final-layer scatter: thread owns true cols {16j+2*c2 .. +3}, j=0..3.
// b3p is the bias stored in permuted (label) order.
__device__ __forceinline__ void scatter_v4(const float acc[8][4], const float* b3p,
                                           float* base0, float* base1,
                                           int d0ok, int d1ok, int c2)
{
#pragma unroll
    for (int j = 0; j < 4; j++) {
        float2 bA = *(const float2*)(b3p + (2 * j) * 8 + c2);
        float2 bB = *(const float2*)(b3p + (2 * j + 1) * 8 + c2);
        int base = 16 * j + 2 * c2;
        if (d0ok) red4(base0 + base, acc[2 * j][0] + bA.x, acc[2 * j][1] + bA.y,
                       acc[2 * j + 1][0] + bB.x, acc[2 * j + 1][1] + bB.y);
        if (d1ok) red4(base1 + base, acc[2 * j][2] + bA.x, acc[2 * j][3] + bA.y,
                       acc[2 * j + 1][2] + bB.x, acc[2 * j + 1][3] + bB.y);
    }
}

// ---------------------------------------------------------------------------
__global__ void zero_kernel(void) {
    int i = blockIdx.x * blockDim.x + threadIdx.x;
    if (i < NS * 64) { g_sum_u[i] = 0.0f; g_sum_x[i] = 0.0f; }
    if (i < NS) g_deg[i] = 0.0f;
}

// ---------------------------------------------------------------------------
// s2s: 77->64->64->64. 256 threads, 128 edges/tile (8 warps x 16 edges).
#define S_W1H 0
#define S_W1L 11264
#define S_W2H 22528
#define S_W2L 31744
#define S_W3H 40960
#define S_W3L 50176
#define S_AH  59392
#define S_AL  81920
#define S_B1  104448
#define S_B2  104704
#define S_B3  104960
#define S_DST 105216
#define S2S_SMEM 105728

__global__ void __launch_bounds__(256, 2) s2s_kernel(
    const float* __restrict__ pos_state, const float* __restrict__ xin,
    const float* __restrict__ hbuf,
    const int* __restrict__ esrc, const int* __restrict__ edst,
    const float* __restrict__ edis,
    const float* __restrict__ W1, const float* __restrict__ B1,
    const float* __restrict__ W2, const float* __restrict__ B2,
    const float* __restrict__ W3, const float* __restrict__ B3)
{
    extern __shared__ char sm[];
    uint32_t* W1h = (uint32_t*)(sm + S_W1H);
    uint32_t* W1l = (uint32_t*)(sm + S_W1L);
    uint32_t* W2h = (uint32_t*)(sm + S_W2H);
    uint32_t* W2l = (uint32_t*)(sm + S_W2L);
    uint32_t* W3h = (uint32_t*)(sm + S_W3H);
    uint32_t* W3l = (uint32_t*)(sm + S_W3L);
    uint32_t* Ah  = (uint32_t*)(sm + S_AH);
    uint32_t* Al  = (uint32_t*)(sm + S_AL);
    float* b1 = (float*)(sm + S_B1);
    float* b2 = (float*)(sm + S_B2);
    float* b3 = (float*)(sm + S_B3);
    int* sdst = (int*)(sm + S_DST);
    int tid = threadIdx.x;

    stage_W(W1, W1h, W1l, 77, 44, tid, 256, 0);
    stage_W(W2, W2h, W2l, 64, 36, tid, 256, 0);
    stage_W(W3, W3h, W3l, 64, 36, tid, 256, 1);
    if (tid < 64) {
        b1[tid] = B1[tid]; b2[tid] = B2[tid];
        b3[perm_L(tid)] = B3[tid];
    }
    __syncthreads();

    int lane = tid & 31, w = tid >> 5;
    int rowbase = w * 16;
    int g = lane >> 2, c2 = (lane & 3) * 2;
    int half = tid & 1, row = tid >> 1;
    const int NT = (ES + 127) / 128;
    bool first = true;

    for (int t = blockIdx.x; t < NT; t += gridDim.x) {
        if (!first) __syncthreads();
        first = false;
        {
            int e = t * 128 + row;
            bool act = e < ES;
            int ec = act ? e : 0;
            int s = esrc[ec], d = edst[ec];
            uint32_t* rh = Ah + row * 44;
            uint32_t* rl = Al + row * 44;
            uint32_t hi, lo;
            const float4* h4 = (const float4*)(hbuf + 64 * (size_t)s);
            if (half == 0) {
                float2 ps = *(const float2*)(pos_state + 2 * (size_t)s);
                float2 pd = *(const float2*)(pos_state + 2 * (size_t)d);
                float dis = edis[ec];
                const float4* x4 = (const float4*)(xin + 8 * (size_t)s);
                float4 xa = x4[0], xb = x4[1];
                split2(ps.x, ps.y, hi, lo); rh[0] = hi; rl[0] = lo;
                split2(pd.x, pd.y, hi, lo); rh[1] = hi; rl[1] = lo;
                split2(dis, xa.x, hi, lo);  rh[2] = hi; rl[2] = lo;
                split2(xa.y, xa.z, hi, lo); rh[3] = hi; rl[3] = lo;
                split2(xa.w, xb.x, hi, lo); rh[4] = hi; rl[4] = lo;
                split2(xb.y, xb.z, hi, lo); rh[5] = hi; rl[5] = lo;
                float prev = xb.w;
#pragma unroll
                for (int i = 0; i < 7; i++) {
                    float4 f = h4[i];
                    split2(prev, f.x, hi, lo); rh[6 + 2 * i] = hi; rl[6 + 2 * i] = lo;
                    split2(f.y, f.z, hi, lo);  rh[7 + 2 * i] = hi; rl[7 + 2 * i] = lo;
                    prev = f.w;
                }
                sdst[row] = act ? d : -1;
                if (act) atomicAdd(g_deg + d, 1.0f);
            } else {
                float4 f6 = h4[6];
                float prev = f6.w;  // h[27]
#pragma unroll
                for (int i = 7; i < 16; i++) {
                    float4 f = h4[i];
                    split2(prev, f.x, hi, lo); rh[6 + 2 * i] = hi; rl[6 + 2 * i] = lo;
                    split2(f.y, f.z, hi, lo);  rh[7 + 2 * i] = hi; rl[7 + 2 * i] = lo;
                    prev = f.w;
                }
                split2(prev, 0.0f, hi, lo); rh[38] = hi; rl[38] = lo;
                rh[39] = 0; rl[39] = 0;
            }
        }
        __syncthreads();

        float acc[8][4];
        uint32_t zh[16], zl[16];
        layer_smem(acc, Ah, Al, 44, rowbase, W1h, W1l, 44, 5, lane);
        epi(acc, b1, zh, zl, lane);
        layer_regs(acc, zh, zl, W2h, W2l, lane);
        epi(acc, b2, zh, zl, lane);
        layer_regs(acc, zh, zl, W3h, W3l, lane);

        int d0 = sdst[rowbase + g], d1 = sdst[rowbase + g + 8];
        scatter_v4(acc, b3,
                   g_sum_x + (size_t)(d0 < 0 ? 0 : d0) * 64,
                   g_sum_x + (size_t)(d1 < 0 ? 0 : d1) * 64,
                   d0 >= 0, d1 >= 0, c2);
    }
}

// ---------------------------------------------------------------------------
// a2s: 13->64->64->64. 256 threads, 128 edges/tile. A/W1 stride 12, kchunks=1.
#define A_W1H 0
#define A_W1L 3072
#define A_W2H 6144
#define A_W2L 15360
#define A_W3H 24576
#define A_W3L 33792
#define A_AH  43008
#define A_AL  49152
#define A_B1  55296
#define A_B2  55552
#define A_B3  55808
#define A_DST 56064
#define A2S_SMEM 56576

__global__ void __launch_bounds__(256, 2) a2s_kernel(
    const float* __restrict__ pos_state, const float* __restrict__ pos_action,
    const float* __restrict__ u,
    const int* __restrict__ esrc, const int* __restrict__ edst,
    const float* __restrict__ edis,
    const float* __restrict__ W1, const float* __restrict__ B1,
    const float* __restrict__ W2, const float* __restrict__ B2,
    const float* __restrict__ W3, const float* __restrict__ B3)
{
    extern __shared__ char sm[];
    uint32_t* W1h = (uint32_t*)(sm + A_W1H);
    uint32_t* W1l = (uint32_t*)(sm + A_W1L);
    uint32_t* W2h = (uint32_t*)(sm + A_W2H);
    uint32_t* W2l = (uint32_t*)(sm + A_W2L);
    uint32_t* W3h = (uint32_t*)(sm + A_W3H);
    uint32_t* W3l = (uint32_t*)(sm + A_W3L);
    uint32_t* Ah  = (uint32_t*)(sm + A_AH);
    uint32_t* Al  = (uint32_t*)(sm + A_AL);
    float* b1 = (float*)(sm + A_B1);
    float* b2 = (float*)(sm + A_B2);
    float* b3 = (float*)(sm + A_B3);
    int* sdst = (int*)(sm + A_DST);
    int tid = threadIdx.x;

    stage_W(W1, W1h, W1l, 13, 12, tid, 256, 0);
    stage_W(W2, W2h, W2l, 64, 36, tid, 256, 0);
    stage_W(W3, W3h, W3l, 64, 36, tid, 256, 1);
    if (tid < 64) {
        b1[tid] = B1[tid]; b2[tid] = B2[tid];
        b3[perm_L(tid)] = B3[tid];
    }
    __syncthreads();

    int lane = tid & 31, w = tid >> 5;
    int rowbase = w * 16;
    int g = lane >> 2, c2 = (lane & 3) * 2;
    int half = tid & 1, row = tid >> 1;
    const int NT = (EA + 127) / 128;
    bool first = true;

    for (int t = blockIdx.x; t < NT; t += gridDim.x) {
        if (!first) __syncthreads();
        first = false;
        {
            int e = t * 128 + row;
            bool act = e < EA;
            int ec = act ? e : 0;
            int s = esrc[ec], d = edst[ec];
            uint32_t* rh = Ah + row * 12;
            uint32_t* rl = Al + row * 12;
            uint32_t hi, lo;
            const float4* u4 = (const float4*)(u + 8 * (size_t)s);
            if (half == 0) {
                float2 pa = *(const float2*)(pos_action + 2 * (size_t)s);
                float2 pd = *(const float2*)(pos_state + 2 * (size_t)d);
                float dis = edis[ec];
                float4 ua = u4[0];
                split2(pa.x, pa.y, hi, lo); rh[0] = hi; rl[0] = lo;
                split2(pd.x, pd.y, hi, lo); rh[1] = hi; rl[1] = lo;
                split2(dis, ua.x, hi, lo);  rh[2] = hi; rl[2] = lo;
                split2(ua.y, ua.z, hi, lo); rh[3] = hi; rl[3] = lo;
                sdst[row] = act ? d : -1;
            } else {
                float4 ua = u4[0], ub = u4[1];
                split2(ua.w, ub.x, hi, lo); rh[4] = hi; rl[4] = lo;
                split2(ub.y, ub.z, hi, lo); rh[5] = hi; rl[5] = lo;
                split2(ub.w, 0.0f, hi, lo); rh[6] = hi; rl[6] = lo;
                rh[7] = 0; rl[7] = 0;
            }
        }
        __syncthreads();

        float acc[8][4];
        uint32_t zh[16], zl[16];
        layer_smem(acc, Ah, Al, 12, rowbase, W1h, W1l, 12, 1, lane);
        epi(acc, b1, zh, zl, lane);
        layer_regs(acc, zh, zl, W2h, W2l, lane);
        epi(acc, b2, zh, zl, lane);
        layer_regs(acc, zh, zl, W3h, W3l, lane);

        int d0 = sdst[rowbase + g], d1 = sdst[rowbase + g + 8];
        scatter_v4(acc, b3,
                   g_sum_u + (size_t)(d0 < 0 ? 0 : d0) * 64,
                   g_sum_u + (size_t)(d1 < 0 ? 0 : d1) * 64,
                   d0 >= 0, d1 >= 0, c2);
    }
}

// ---------------------------------------------------------------------------
// upd: 202->64->64->64. 256 threads, 128 nodes/tile. A/W1 stride 108, kchunks=13.
#define U_W1H 0
#define U_W1L 27648
#define U_W2H 55296
#define U_W2L 64512
#define U_W3H 73728
#define U_W3L 82944
#define U_AH  92160
#define U_AL  147456
#define U_B1  202752
#define U_B2  203008
#define U_B3  203264
#define UPD_SMEM 203520

__global__ void __launch_bounds__(256, 1) upd_kernel(
    const float* __restrict__ pos_state, const float* __restrict__ hbuf,
    const float* __restrict__ xin,
    const float* __restrict__ W1, const float* __restrict__ B1,
    const float* __restrict__ W2, const float* __restrict__ B2,
    const float* __restrict__ W3, const float* __restrict__ B3,
    float* __restrict__ out)
{
    extern __shared__ char sm[];
    uint32_t* W1h = (uint32_t*)(sm + U_W1H);
    uint32_t* W1l = (uint32_t*)(sm + U_W1L);
    uint32_t* W2h = (uint32_t*)(sm + U_W2H);
    uint32_t* W2l = (uint32_t*)(sm + U_W2L);
    uint32_t* W3h = (uint32_t*)(sm + U_W3H);
    uint32_t* W3l = (uint32_t*)(sm + U_W3L);
    uint32_t* Ah  = (uint32_t*)(sm + U_AH);
    uint32_t* Al  = (uint32_t*)(sm + U_AL);
    float* b1 = (float*)(sm + U_B1);
    float* b2 = (float*)(sm + U_B2);
    float* b3 = (float*)(sm + U_B3);
    int tid = threadIdx.x;

    stage_W(W1, W1h, W1l, 202, 108, tid, 256, 0);
    stage_W(W2, W2h, W2l, 64, 36, tid, 256, 0);
    stage_W(W3, W3h, W3l, 64, 36, tid, 256, 1);
    if (tid < 64) {
        b1[tid] = B1[tid]; b2[tid] = B2[tid];
        b3[perm_L(tid)] = B3[tid];
    }
    __syncthreads();

    int lane = tid & 31, w = tid >> 5;
    int rowbase = w * 16;
    int g = lane >> 2, c2 = (lane & 3) * 2;
    int half = tid & 1, row = tid >> 1;
    const int NT = (NS + 127) / 128;
    bool first = true;

    for (int t = blockIdx.x; t < NT; t += gridDim.x) {
        if (!first) __syncthreads();
        first = false;
        {
            int n = t * 128 + row;
            int nc = (n < NS) ? n : 0;
            uint32_t* rh = Ah + row * 108;
            uint32_t* rl = Al + row * 108;
            uint32_t hi, lo;
            if (half == 0) {
                float2 ps = *(const float2*)(pos_state + 2 * (size_t)nc);
                split2(ps.x, ps.y, hi, lo); rh[0] = hi; rl[0] = lo;
                const float4* h4 = (const float4*)(hbuf + 64 * (size_t)nc);
#pragma unroll 4
                for (int i = 0; i < 16; i++) {
                    float4 v = h4[i];
                    split2(v.x, v.y, hi, lo); rh[1 + 2 * i] = hi; rl[1 + 2 * i] = lo;
                    split2(v.z, v.w, hi, lo); rh[2 + 2 * i] = hi; rl[2 + 2 * i] = lo;
                }
                const float4* su4 = (const float4*)(g_sum_u + 64 * (size_t)nc);
#pragma unroll 4
                for (int i = 0; i < 9; i++) {
                    float4 v = su4[i];
                    split2(v.x, v.y, hi, lo); rh[33 + 2 * i] = hi; rl[33 + 2 * i] = lo;
                    split2(v.z, v.w, hi, lo); rh[34 + 2 * i] = hi; rl[34 + 2 * i] = lo;
                }
                float4 v9 = su4[9];
                split2(v9.x, v9.y, hi, lo); rh[51] = hi; rl[51] = lo;
            } else {
                const float4* su4 = (const float4*)(g_sum_u + 64 * (size_t)nc);
                float4 v9 = su4[9];
                split2(v9.z, v9.w, hi, lo); rh[52] = hi; rl[52] = lo;
#pragma unroll 2
                for (int i = 10; i < 16; i++) {
                    float4 v = su4[i];
                    split2(v.x, v.y, hi, lo); rh[33 + 2 * i] = hi; rl[33 + 2 * i] = lo;
                    split2(v.z, v.w, hi, lo); rh[34 + 2 * i] = hi; rl[34 + 2 * i] = lo;
                }
                float inv = rcp_fma(fmaxf(g_deg[nc], 1.0f));
                const float4* sx4 = (const float4*)(g_sum_x + 64 * (size_t)nc);
#pragma unroll 4
                for (int i = 0; i < 16; i++) {
                    float4 v = sx4[i];
                    split2(v.x * inv, v.y * inv, hi, lo); rh[65 + 2 * i] = hi; rl[65 + 2 * i] = lo;
                    split2(v.z * inv, v.w * inv, hi, lo); rh[66 + 2 * i] = hi; rl[66 + 2 * i] = lo;
                }
                const float4* x4 = (const float4*)(xin + 8 * (size_t)nc);
                float4 xa = x4[0], xb = x4[1];
                split2(xa.x, xa.y, hi, lo); rh[97] = hi;  rl[97] = lo;
                split2(xa.z, xa.w, hi, lo); rh[98] = hi;  rl[98] = lo;
                split2(xb.x, xb.y, hi, lo); rh[99] = hi;  rl[99] = lo;
                split2(xb.z, xb.w, hi, lo); rh[100] = hi; rl[100] = lo;
                rh[101] = 0; rl[101] = 0;
                rh[102] = 0; rl[102] = 0;
                rh[103] = 0; rl[103] = 0;
            }
        }
        __syncthreads();

        float acc[8][4];
        uint32_t zh[16], zl[16];
        layer_smem(acc, Ah, Al, 108, rowbase, W1h, W1l, 108, 13, lane);
        epi(acc, b1, zh, zl, lane);
        layer_regs(acc, zh, zl, W2h, W2l, lane);
        epi(acc, b2, zh, zl, lane);
        layer_regs(acc, zh, zl, W3h, W3l, lane);

        int n0 = t * 128 + rowbase + g;
        int n1 = n0 + 8;
#pragma unroll
        for (int j = 0; j < 4; j++) {
            float2 bA = *(const float2*)(b3 + (2 * j) * 8 + c2);
            float2 bB = *(const float2*)(b3 + (2 * j + 1) * 8 + c2);
            int base = 16 * j + 2 * c2;
            if (n0 < NS)
                *(float4*)(out + (size_t)n0 * 64 + base) =
                    make_float4(acc[2 * j][0] + bA.x, acc[2 * j][1] + bA.y,
                                acc[2 * j + 1][0] + bB.x, acc[2 * j + 1][1] + bB.y);
            if (n1 < NS)
                *(float4*)(out + (size_t)n1 * 64 + base) =
                    make_float4(acc[2 * j][2] + bA.x, acc[2 * j][3] + bA.y,
                                acc[2 * j + 1][2] + bB.x, acc[2 * j + 1][3] + bB.y);
        }
    }
}

// ---------------------------------------------------------------------------
extern "C" void kernel_launch(void* const* d_in, const int* in_sizes, int n_in,
                              void* d_out, int out_size) {
    const float* pos_state  = (const float*)d_in[0];
    const float* pos_action = (const float*)d_in[1];
    const float* h          = (const float*)d_in[2];
    const float* x          = (const float*)d_in[3];
    const float* u          = (const float*)d_in[4];
    const int*   a2s_src    = (const int*)d_in[5];
    const int*   a2s_dst    = (const int*)d_in[6];
    const float* a2s_dis    = (const float*)d_in[7];
    const int*   s2s_src    = (const int*)d_in[8];
    const int*   s2s_dst    = (const int*)d_in[9];
    const float* s2s_dis    = (const float*)d_in[10];
    const float* u2h_w1 = (const float*)d_in[11];
    const float* u2h_b1 = (const float*)d_in[12];
    const float* u2h_w2 = (const float*)d_in[13];
    const float* u2h_b2 = (const float*)d_in[14];
    const float* u2h_w3 = (const float*)d_in[15];
    const float* u2h_b3 = (const float*)d_in[16];
    const float* x2h_w1 = (const float*)d_in[17];
    const float* x2h_b1 = (const float*)d_in[18];
    const float* x2h_w2 = (const float*)d_in[19];
    const float* x2h_b2 = (const float*)d_in[20];
    const float* x2h_w3 = (const float*)d_in[21];
    const float* x2h_b3 = (const float*)d_in[22];
    const float* upd_w1 = (const float*)d_in[23];
    const float* upd_b1 = (const float*)d_in[24];
    const float* upd_w2 = (const float*)d_in[25];
    const float* upd_b2 = (const float*)d_in[26];
    const float* upd_w3 = (const float*)d_in[27];
    const float* upd_b3 = (const float*)d_in[28];
    float* out = (float*)d_out;

    cudaFuncSetAttribute(s2s_kernel, cudaFuncAttributeMaxDynamicSharedMemorySize, S2S_SMEM);
    cudaFuncSetAttribute(a2s_kernel, cudaFuncAttributeMaxDynamicSharedMemorySize, A2S_SMEM);
    cudaFuncSetAttribute(upd_kernel, cudaFuncAttributeMaxDynamicSharedMemorySize, UPD_SMEM);

    zero_kernel<<<(NS * 64 + 255) / 256, 256>>>();

    a2s_kernel<<<296, 256, A2S_SMEM>>>(
        pos_state, pos_action, u, a2s_src, a2s_dst, a2s_dis,
        u2h_w1, u2h_b1, u2h_w2, u2h_b2, u2h_w3, u2h_b3);

    s2s_kernel<<<296, 256, S2S_SMEM>>>(
        pos_state, x, h, s2s_src, s2s_dst, s2s_dis,
        x2h_w1, x2h_b1, x2h_w2, x2h_b2, x2h_w3, x2h_b3);

    upd_kernel<<<148, 256, UPD_SMEM>>>(
        pos_state, h, x,
        upd_w1, upd_b1, upd_w2, upd_b2, upd_w3, upd_b3,
        out);
}